// round 13
// baseline (speedup 1.0000x reference)
#include <cuda_runtime.h>
#include <cuda_fp16.h>
#include <math.h>
#include <stdint.h>

// Problem constants
#define B_   2
#define S_   2048
#define D_   2048
#define H_   16
#define HD_  128
#define DFF_ 8192
#define BS_  4096            // B_*S_
#define EPS_ 1e-5f

// ---------------- scratch (device globals; no allocations allowed) ----------
__device__ __half g_h   [BS_ * D_];       // LN out (fp16, feeds GEMMs only)
__device__ float  g_q   [BS_ * D_];       // Q in [B,H,S,HD] (fp32, attention)
__device__ float  g_k   [BS_ * D_];
__device__ float  g_v   [BS_ * D_];
__device__ __half g_attn[BS_ * D_];       // attn out (fp16, feeds WO GEMM)
__device__ float  g_x2  [BS_ * D_];       // residual after attention (fp32)
__device__ __half g_ff  [BS_ * DFF_];     // GELU out (fp16, feeds W2 GEMM)

// fp16 weights, pair-interleaved: Wp[kp][n] = {lo=W[2kp][n], hi=W[2kp+1][n]}
__device__ uint32_t g_wq[D_ * D_ / 2];
__device__ uint32_t g_wk[D_ * D_ / 2];
__device__ uint32_t g_wv[D_ * D_ / 2];
__device__ uint32_t g_wo[D_ * D_ / 2];
__device__ uint32_t g_w1[D_ * DFF_ / 2];
__device__ uint32_t g_w2[DFF_ * D_ / 2];

__device__ __forceinline__ uint32_t pack2(float lo, float hi) {
    __half2 h = __floats2half2_rn(lo, hi);
    return *reinterpret_cast<uint32_t*>(&h);
}

// ================= weight conversion: fp32 [K,N] -> u32 pairs [K/2,N] =======
__global__ void __launch_bounds__(256) cvt_pair_kernel(
    const float* __restrict__ W, uint32_t* __restrict__ Wp, int N, int total)
{
    const int i = blockIdx.x * 256 + threadIdx.x;   // one uint4 (4 pairs)
    if (i >= total) return;
    const int n4 = N >> 2;
    const int kp = i / n4;
    const int n0 = (i - kp * n4) * 4;
    const float4 r0 = *(const float4*)(W + (size_t)(2 * kp) * N + n0);
    const float4 r1 = *(const float4*)(W + (size_t)(2 * kp + 1) * N + n0);
    uint4 o;
    o.x = pack2(r0.x, r1.x);
    o.y = pack2(r0.y, r1.y);
    o.z = pack2(r0.z, r1.z);
    o.w = pack2(r0.w, r1.w);
    *(uint4*)(Wp + (size_t)kp * N + n0) = o;
}

// ============================ LayerNorm (fp16 out) ==========================
__global__ void __launch_bounds__(256) ln_kernel(const float* __restrict__ x,
                                                 const float* __restrict__ gam,
                                                 const float* __restrict__ bet,
                                                 __half* __restrict__ out)
{
    __shared__ float red[8];
    __shared__ float s_mu, s_rstd;
    const int row = blockIdx.x;
    const int t   = threadIdx.x;
    const float* xr = x + (size_t)row * D_;

    float4 v0 = *(const float4*)(xr + t * 4);
    float4 v1 = *(const float4*)(xr + 1024 + t * 4);

    float s = v0.x + v0.y + v0.z + v0.w + v1.x + v1.y + v1.z + v1.w;
    #pragma unroll
    for (int o = 16; o; o >>= 1) s += __shfl_xor_sync(0xffffffffu, s, o);
    if ((t & 31) == 0) red[t >> 5] = s;
    __syncthreads();
    if (t == 0) {
        float a = 0.f;
        #pragma unroll
        for (int i = 0; i < 8; i++) a += red[i];
        s_mu = a * (1.0f / D_);
    }
    __syncthreads();
    const float mu = s_mu;

    float dx[8];
    dx[0]=v0.x-mu; dx[1]=v0.y-mu; dx[2]=v0.z-mu; dx[3]=v0.w-mu;
    dx[4]=v1.x-mu; dx[5]=v1.y-mu; dx[6]=v1.z-mu; dx[7]=v1.w-mu;
    float sq = 0.f;
    #pragma unroll
    for (int i = 0; i < 8; i++) sq += dx[i]*dx[i];
    #pragma unroll
    for (int o = 16; o; o >>= 1) sq += __shfl_xor_sync(0xffffffffu, sq, o);
    __syncthreads();
    if ((t & 31) == 0) red[t >> 5] = sq;
    __syncthreads();
    if (t == 0) {
        float a = 0.f;
        #pragma unroll
        for (int i = 0; i < 8; i++) a += red[i];
        s_rstd = rsqrtf(a * (1.0f / D_) + EPS_);
    }
    __syncthreads();
    const float rstd = s_rstd;

    __half* orow = out + (size_t)row * D_;
    const int c0 = t * 4, c1 = 1024 + t * 4;
    float4 gv0 = *(const float4*)(gam + c0);
    float4 gv1 = *(const float4*)(gam + c1);
    float4 bv0 = *(const float4*)(bet + c0);
    float4 bv1 = *(const float4*)(bet + c1);
    uint2 p0, p1;
    p0.x = pack2(dx[0]*rstd*gv0.x + bv0.x, dx[1]*rstd*gv0.y + bv0.y);
    p0.y = pack2(dx[2]*rstd*gv0.z + bv0.z, dx[3]*rstd*gv0.w + bv0.w);
    p1.x = pack2(dx[4]*rstd*gv1.x + bv1.x, dx[5]*rstd*gv1.y + bv1.y);
    p1.y = pack2(dx[6]*rstd*gv1.z + bv1.z, dx[7]*rstd*gv1.w + bv1.w);
    *(uint2*)(orow + c0) = p0;
    *(uint2*)(orow + c1) = p1;
}

// ============================ common tensor-core helpers ====================
__device__ __forceinline__ uint32_t f2tf(float x) {
    uint32_t r;
    asm("cvt.rna.tf32.f32 %0, %1;" : "=r"(r) : "f"(x));
    return r;
}

__device__ __forceinline__ void mma8(float* c, const uint32_t* a, const uint32_t* b) {
    asm volatile(
        "mma.sync.aligned.m16n8k8.row.col.f32.tf32.tf32.f32 "
        "{%0,%1,%2,%3}, {%4,%5,%6,%7}, {%8,%9}, {%0,%1,%2,%3};"
        : "+f"(c[0]), "+f"(c[1]), "+f"(c[2]), "+f"(c[3])
        : "r"(a[0]), "r"(a[1]), "r"(a[2]), "r"(a[3]), "r"(b[0]), "r"(b[1]));
}

__device__ __forceinline__ void mma16(float* c, const uint32_t* a, const uint32_t* b) {
    asm volatile(
        "mma.sync.aligned.m16n8k16.row.col.f32.f16.f16.f32 "
        "{%0,%1,%2,%3}, {%4,%5,%6,%7}, {%8,%9}, {%0,%1,%2,%3};"
        : "+f"(c[0]), "+f"(c[1]), "+f"(c[2]), "+f"(c[3])
        : "r"(a[0]), "r"(a[1]), "r"(a[2]), "r"(a[3]), "r"(b[0]), "r"(b[1]));
}

#define CPA16(dst, src) \
    asm volatile("cp.async.cg.shared.global [%0], [%1], 16;\n" :: "r"(dst), "l"(src))

// ============================ FP16 tensor-core GEMM =========================
// C[M,N] = A[M,K] @ W[K,N] (+bias). A: fp16 row-major. W: u32 k-pair [K/2,N].
// 128x128x32 tile, 256 threads (8 warps 2x4, 64x32 warp tiles),
// mma.m16n8k16.f16, fp32 accum, cp.async double buffer.
#define M_PERM 0
#define M_RES  1
#define M_GELU 2

#define ASTRU 20    // u32 stride of A smem rows (16 kp + 4 pad) -> CF frags
#define BSTRU 136   // u32 stride of B smem rows -> CF frags

template<int MODE>
__global__ void __launch_bounds__(256) hgemm_kernel(
    const __half* __restrict__ A, const uint32_t* __restrict__ Wp,
    const float* __restrict__ bias, const float* __restrict__ res,
    void* __restrict__ outv, int M, int N, int K)
{
    __shared__ uint32_t As[2][128][ASTRU];   // 20.0 KB
    __shared__ uint32_t Bs[2][16][BSTRU];    // 17.0 KB

    const int t    = threadIdx.x;
    const int bm   = blockIdx.y * 128;
    const int bn   = blockIdx.x * 128;
    const int warp = t >> 5, lane = t & 31;
    const int wm   = warp >> 2, wn = warp & 3;   // 2x4 warp grid
    const int lg   = lane >> 2, lk = lane & 3;

    // A: slot i in {0,1}: row = (t>>2)+64i, 16B unit c = t&3 (8 fp16 = 4 kp)
    const int a_row = t >> 2, a_c = t & 3;
    // B: slot i: kp = (t>>5)+8i, n0 = 4*(t&31) u32
    const int b_kp = t >> 5, b_n = (t & 31) * 4;

    const uint32_t dA0 = (uint32_t)__cvta_generic_to_shared(&As[0][a_row][4 * a_c]);
    const uint32_t dA1 = (uint32_t)__cvta_generic_to_shared(&As[0][64 + a_row][4 * a_c]);
    const uint32_t dB0 = (uint32_t)__cvta_generic_to_shared(&Bs[0][b_kp][b_n]);
    const uint32_t dB1 = (uint32_t)__cvta_generic_to_shared(&Bs[0][8 + b_kp][b_n]);
    const uint32_t aBuf = 128 * ASTRU * 4;
    const uint32_t bBuf = 16 * BSTRU * 4;

    const __half*   gA0 = A + (size_t)(bm + a_row) * K + 8 * a_c;
    const __half*   gA1 = A + (size_t)(bm + 64 + a_row) * K + 8 * a_c;
    const uint32_t* gB0 = Wp + (size_t)b_kp * N + bn + b_n;
    const uint32_t* gB1 = Wp + (size_t)(8 + b_kp) * N + bn + b_n;

    float acc[4][4][4];
    #pragma unroll
    for (int i = 0; i < 4; i++)
        #pragma unroll
        for (int j = 0; j < 4; j++)
            #pragma unroll
            for (int r = 0; r < 4; r++) acc[i][j][r] = 0.f;

    const int KT = K >> 5;   // K-chunks of 32

    CPA16(dA0, gA0);
    CPA16(dA1, gA1);
    CPA16(dB0, gB0);
    CPA16(dB1, gB1);
    asm volatile("cp.async.commit_group;");

    int buf = 0;
    for (int kt = 0; kt < KT; ++kt) {
        if (kt + 1 < KT) {
            const uint32_t bo = (uint32_t)(buf ^ 1);
            const size_t ka = (size_t)(kt + 1) * 32;         // fp16 elems
            const size_t kb = (size_t)(kt + 1) * 16 * N;     // u32 elems
            CPA16(dA0 + bo * aBuf, gA0 + ka);
            CPA16(dA1 + bo * aBuf, gA1 + ka);
            CPA16(dB0 + bo * bBuf, gB0 + kb);
            CPA16(dB1 + bo * bBuf, gB1 + kb);
            asm volatile("cp.async.commit_group;");
            asm volatile("cp.async.wait_group 1;");
        } else {
            asm volatile("cp.async.wait_group 0;");
        }
        __syncthreads();

        #pragma unroll
        for (int s = 0; s < 2; ++s) {           // two k16 steps per chunk
            const int kb8 = s * 8;
            uint32_t af[4][4], bf[4][2];
            #pragma unroll
            for (int mt = 0; mt < 4; ++mt) {
                const uint32_t* ap = &As[buf][wm * 64 + mt * 16 + lg][kb8 + lk];
                af[mt][0] = ap[0];
                af[mt][1] = ap[8 * ASTRU];
                af[mt][2] = ap[4];
                af[mt][3] = ap[8 * ASTRU + 4];
            }
            #pragma unroll
            for (int nt = 0; nt < 4; ++nt) {
                const int col = wn * 32 + nt * 8 + lg;
                bf[nt][0] = Bs[buf][kb8 + lk][col];
                bf[nt][1] = Bs[buf][kb8 + lk + 4][col];
            }
            #pragma unroll
            for (int mt = 0; mt < 4; ++mt)
                #pragma unroll
                for (int nt = 0; nt < 4; ++nt)
                    mma16(acc[mt][nt], af[mt], bf[nt]);
        }
        __syncthreads();
        buf ^= 1;
    }

    // epilogue
    #pragma unroll
    for (int mt = 0; mt < 4; ++mt) {
        #pragma unroll
        for (int nt = 0; nt < 4; ++nt) {
            const int r0 = bm + wm * 64 + mt * 16 + lg;
            const int c  = bn + wn * 32 + nt * 8 + lk * 2;
            const float b0 = bias[c], b1 = bias[c + 1];
            #pragma unroll
            for (int half = 0; half < 2; ++half) {
                const int r = r0 + half * 8;
                float v0 = acc[mt][nt][half * 2 + 0] + b0;
                float v1 = acc[mt][nt][half * 2 + 1] + b1;
                if (MODE == M_PERM) {
                    float* out = (float*)outv;
                    const int bb = r >> 11, ss = r & (S_ - 1);
                    const int hh = c >> 7,  dd = c & (HD_ - 1);
                    const size_t idx = ((((size_t)bb * H_ + hh) * S_ + ss) << 7) + dd;
                    float2 w; w.x = v0; w.y = v1;
                    *(float2*)(out + idx) = w;
                } else if (MODE == M_RES) {
                    float* out = (float*)outv;
                    const size_t idx = (size_t)r * N + c;
                    float2 rv = *(const float2*)(res + idx);
                    float2 w; w.x = v0 + rv.x; w.y = v1 + rv.y;
                    *(float2*)(out + idx) = w;
                } else { // GELU (exact, erf) -> fp16
                    __half* out = (__half*)outv;
                    const size_t idx = (size_t)r * N + c;
                    const float g0 = 0.5f * v0 * (1.0f + erff(v0 * 0.70710678118654752f));
                    const float g1 = 0.5f * v1 * (1.0f + erff(v1 * 0.70710678118654752f));
                    *(uint32_t*)(out + idx) = pack2(g0, g1);
                }
            }
        }
    }
}

// ==================== TF32 tensor-core flash attention ======================
// grid (S/64, H, B), 256 threads (8 warps). BQ=64, BK=64, HD=128.
#define BQ_   64
#define BKT_  64
#define QSTR  132
#define VSTR  136
#define SSTR  68

__global__ void __launch_bounds__(256) attn_kernel(
    const float* __restrict__ Qg, const float* __restrict__ Kg,
    const float* __restrict__ Vg, const int* __restrict__ amask,
    __half* __restrict__ out)
{
    extern __shared__ float sm[];
    float* Qs   = sm;                              // 64*132 (tf32 bits)
    float* Ks   = Qs + BQ_ * QSTR;                 // 2 * 64*132
    float* Vs   = Ks + 2 * BKT_ * QSTR;            // 2 * 64*136
    float* Ss   = Vs + 2 * BKT_ * VSTR;            // 64*68
    float* mrow = Ss + BQ_ * SSTR;                 // 64
    float* lrow = mrow + BQ_;                      // 64
    float* arow = lrow + BQ_;                      // 64
    int*   msk  = (int*)(arow + BQ_);              // 2 * 64

    const int t    = threadIdx.x;
    const int warp = t >> 5, lane = t & 31;
    const int lg   = lane >> 2, lk = lane & 3;
    const int wm   = warp >> 1, wn = warp & 1;     // 4x2 warp grid
    const int bq0  = blockIdx.x * BQ_;
    const int h    = blockIdx.y;
    const int b    = blockIdx.z;
    const size_t base = ((size_t)(b * H_ + h) * S_) * HD_;
    const float scale = 0.08838834764831845f;      // 1/sqrt(128)

    const uint32_t ksb  = (uint32_t)__cvta_generic_to_shared(Ks);
    const uint32_t vsb  = (uint32_t)__cvta_generic_to_shared(Vs);
    const uint32_t mskb = (uint32_t)__cvta_generic_to_shared(msk);
    const uint32_t KBUF = BKT_ * QSTR * 4;
    const uint32_t VBUF = BKT_ * VSTR * 4;

    #pragma unroll
    for (int r = 0; r < 8; ++r) {
        const int e = t * 4 + r * 1024;
        const int row = e >> 7, col = e & 127;
        float4 v = *(const float4*)(Qg + base + (size_t)(bq0 + row) * HD_ + col);
        float* dst = &Qs[row * QSTR + col];
        dst[0] = __uint_as_float(f2tf(v.x * scale));
        dst[1] = __uint_as_float(f2tf(v.y * scale));
        dst[2] = __uint_as_float(f2tf(v.z * scale));
        dst[3] = __uint_as_float(f2tf(v.w * scale));
    }
    if (t < BQ_) { mrow[t] = -1e30f; lrow[t] = 0.0f; }

    const int nkt = blockIdx.x + 1;

    {
        const int k0 = 0;
        #pragma unroll
        for (int r = 0; r < 8; ++r) {
            const int e = t * 4 + r * 1024;
            const int row = e >> 7, col = e & 127;
            CPA16(ksb + (uint32_t)(row * QSTR + col) * 4,
                  Kg + base + (size_t)(k0 + row) * HD_ + col);
            CPA16(vsb + (uint32_t)(row * VSTR + col) * 4,
                  Vg + base + (size_t)(k0 + row) * HD_ + col);
        }
        if (t < 16) CPA16(mskb + t * 16, amask + b * S_ + k0 + t * 4);
        asm volatile("cp.async.commit_group;");
    }

    float o[8][4];
    #pragma unroll
    for (int i = 0; i < 8; i++)
        #pragma unroll
        for (int r = 0; r < 4; r++) o[i][r] = 0.f;

    const int r0  = 16 * wm + lg;
    const uint32_t* Qu = (const uint32_t*)Qs;

    int buf = 0;
    for (int kt = 0; kt < nkt; ++kt) {
        const int k0 = kt * BKT_;
        asm volatile("cp.async.wait_group 0;");
        __syncthreads();

        if (kt + 1 < nkt) {
            const int kn = (kt + 1) * BKT_;
            const uint32_t bo = (uint32_t)(buf ^ 1);
            #pragma unroll
            for (int r = 0; r < 8; ++r) {
                const int e = t * 4 + r * 1024;
                const int row = e >> 7, col = e & 127;
                CPA16(ksb + bo * KBUF + (uint32_t)(row * QSTR + col) * 4,
                      Kg + base + (size_t)(kn + row) * HD_ + col);
                CPA16(vsb + bo * VBUF + (uint32_t)(row * VSTR + col) * 4,
                      Vg + base + (size_t)(kn + row) * HD_ + col);
            }
            if (t < 16) CPA16(mskb + bo * 256 + t * 16, amask + b * S_ + kn + t * 4);
            asm volatile("cp.async.commit_group;");
        }

        const float* Kb = Ks + buf * BKT_ * QSTR;
        const float* Vb = Vs + buf * BKT_ * VSTR;
        const int*   mb = msk + buf * BKT_;

        float c[4][4];
        #pragma unroll
        for (int i = 0; i < 4; i++)
            #pragma unroll
            for (int r = 0; r < 4; r++) c[i][r] = 0.f;

        #pragma unroll
        for (int k8 = 0; k8 < HD_; k8 += 8) {
            uint32_t af[4], bfv[4][2];
            const uint32_t* qp = &Qu[r0 * QSTR + k8 + lk];
            af[0] = qp[0];
            af[1] = qp[8 * QSTR];
            af[2] = qp[4];
            af[3] = qp[8 * QSTR + 4];
            #pragma unroll
            for (int nt = 0; nt < 4; ++nt) {
                const int col = 32 * wn + nt * 8 + lg;
                bfv[nt][0] = f2tf(Kb[col * QSTR + k8 + lk]);
                bfv[nt][1] = f2tf(Kb[col * QSTR + k8 + lk + 4]);
            }
            #pragma unroll
            for (int nt = 0; nt < 4; ++nt) mma8(c[nt], af, bfv[nt]);
        }

        const bool diag = (kt == nkt - 1);
        const int qg0 = bq0 + r0, qg1 = qg0 + 8;
        #pragma unroll
        for (int nt = 0; nt < 4; ++nt) {
            const int jl0 = 32 * wn + nt * 8 + 2 * lk;
            const int jl1 = jl0 + 1;
            const int jg0 = k0 + jl0, jg1 = jg0 + 1;
            const bool m0 = (mb[jl0] != 0), m1 = (mb[jl1] != 0);
            const bool v00 = m0 && (!diag || jg0 <= qg0);
            const bool v01 = m1 && (!diag || jg1 <= qg0);
            const bool v10 = m0 && (!diag || jg0 <= qg1);
            const bool v11 = m1 && (!diag || jg1 <= qg1);
            Ss[r0 * SSTR + jl0]       = v00 ? c[nt][0] : -1e30f;
            Ss[r0 * SSTR + jl1]       = v01 ? c[nt][1] : -1e30f;
            Ss[(r0 + 8) * SSTR + jl0] = v10 ? c[nt][2] : -1e30f;
            Ss[(r0 + 8) * SSTR + jl1] = v11 ? c[nt][3] : -1e30f;
        }
        __syncthreads();

        {
            const int sr  = t >> 2;
            const int sc0 = (t & 3) * 16;
            float4 va = *(const float4*)&Ss[sr * SSTR + sc0];
            float4 vb = *(const float4*)&Ss[sr * SSTR + sc0 + 4];
            float4 vc = *(const float4*)&Ss[sr * SSTR + sc0 + 8];
            float4 vd = *(const float4*)&Ss[sr * SSTR + sc0 + 12];
            float tmax = fmaxf(fmaxf(fmaxf(va.x, va.y), fmaxf(va.z, va.w)),
                               fmaxf(fmaxf(vb.x, vb.y), fmaxf(vb.z, vb.w)));
            tmax = fmaxf(tmax,
                   fmaxf(fmaxf(fmaxf(vc.x, vc.y), fmaxf(vc.z, vc.w)),
                         fmaxf(fmaxf(vd.x, vd.y), fmaxf(vd.z, vd.w))));
            tmax = fmaxf(tmax, __shfl_xor_sync(0xffffffffu, tmax, 1));
            tmax = fmaxf(tmax, __shfl_xor_sync(0xffffffffu, tmax, 2));
            const float mo = mrow[sr];
            const float nm = fmaxf(mo, tmax);
            va.x = __expf(va.x - nm); va.y = __expf(va.y - nm);
            va.z = __expf(va.z - nm); va.w = __expf(va.w - nm);
            vb.x = __expf(vb.x - nm); vb.y = __expf(vb.y - nm);
            vb.z = __expf(vb.z - nm); vb.w = __expf(vb.w - nm);
            vc.x = __expf(vc.x - nm); vc.y = __expf(vc.y - nm);
            vc.z = __expf(vc.z - nm); vc.w = __expf(vc.w - nm);
            vd.x = __expf(vd.x - nm); vd.y = __expf(vd.y - nm);
            vd.z = __expf(vd.z - nm); vd.w = __expf(vd.w - nm);
            float sum = va.x + va.y + va.z + va.w + vb.x + vb.y + vb.z + vb.w +
                        vc.x + vc.y + vc.z + vc.w + vd.x + vd.y + vd.z + vd.w;
            *(float4*)&Ss[sr * SSTR + sc0]      = va;
            *(float4*)&Ss[sr * SSTR + sc0 + 4]  = vb;
            *(float4*)&Ss[sr * SSTR + sc0 + 8]  = vc;
            *(float4*)&Ss[sr * SSTR + sc0 + 12] = vd;
            sum += __shfl_xor_sync(0xffffffffu, sum, 1);
            sum += __shfl_xor_sync(0xffffffffu, sum, 2);
            if ((t & 3) == 0) {
                const float al = __expf(mo - nm);
                arow[sr] = al;
                lrow[sr] = lrow[sr] * al + sum;
                mrow[sr] = nm;
            }
        }
        __syncthreads();

        const float al0 = arow[r0];
        const float al1 = arow[r0 + 8];
        #pragma unroll
        for (int nt = 0; nt < 8; ++nt) {
            o[nt][0] *= al0; o[nt][1] *= al0;
            o[nt][2] *= al1; o[nt][3] *= al1;
        }
        #pragma unroll
        for (int k8 = 0; k8 < BKT_; k8 += 8) {
            uint32_t af[4], bfv[8][2];
            const float* pp = &Ss[r0 * SSTR + k8 + lk];
            af[0] = f2tf(pp[0]);
            af[1] = f2tf(pp[8 * SSTR]);
            af[2] = f2tf(pp[4]);
            af[3] = f2tf(pp[8 * SSTR + 4]);
            #pragma unroll
            for (int nt = 0; nt < 8; ++nt) {
                const int n = 64 * wn + nt * 8 + lg;
                bfv[nt][0] = f2tf(Vb[(k8 + lk) * VSTR + n]);
                bfv[nt][1] = f2tf(Vb[(k8 + lk + 4) * VSTR + n]);
            }
            #pragma unroll
            for (int nt = 0; nt < 8; ++nt) mma8(o[nt], af, bfv[nt]);
        }
        buf ^= 1;
    }

    // epilogue: normalize, write fp16 to [B,S,D] with head de-interleave
    const float inv0 = 1.0f / lrow[r0];
    const float inv1 = 1.0f / lrow[r0 + 8];
    #pragma unroll
    for (int nt = 0; nt < 8; ++nt) {
        const int col = 64 * wn + nt * 8 + 2 * lk;
        const size_t base0 = ((size_t)b * S_ + bq0 + r0) * D_ + h * HD_ + col;
        const size_t base1 = base0 + (size_t)8 * D_;
        *(uint32_t*)(out + base0) = pack2(o[nt][0] * inv0, o[nt][1] * inv0);
        *(uint32_t*)(out + base1) = pack2(o[nt][2] * inv1, o[nt][3] * inv1);
    }
}

// ============================ launch ========================================
extern "C" void kernel_launch(void* const* d_in, const int* in_sizes, int n_in,
                              void* d_out, int out_size)
{
    const float* x     = (const float*)d_in[0];
    const int*   amask = (const int*)  d_in[1];
    const float* ln1_g = (const float*)d_in[2];
    const float* ln1_b = (const float*)d_in[3];
    const float* wq    = (const float*)d_in[4];
    const float* bq    = (const float*)d_in[5];
    const float* wk    = (const float*)d_in[6];
    const float* bk    = (const float*)d_in[7];
    const float* wv    = (const float*)d_in[8];
    const float* bv    = (const float*)d_in[9];
    const float* wo    = (const float*)d_in[10];
    const float* bo    = (const float*)d_in[11];
    const float* ln2_g = (const float*)d_in[12];
    const float* ln2_b = (const float*)d_in[13];
    const float* w1    = (const float*)d_in[14];
    const float* b1    = (const float*)d_in[15];
    const float* w2    = (const float*)d_in[16];
    const float* b2    = (const float*)d_in[17];
    float* outp = (float*)d_out;

    __half *ph, *pattn, *pff;
    float *pq, *pk, *pv, *px2;
    uint32_t *pwq, *pwk, *pwv, *pwo, *pw1, *pw2;
    cudaGetSymbolAddress((void**)&ph,    g_h);
    cudaGetSymbolAddress((void**)&pq,    g_q);
    cudaGetSymbolAddress((void**)&pk,    g_k);
    cudaGetSymbolAddress((void**)&pv,    g_v);
    cudaGetSymbolAddress((void**)&pattn, g_attn);
    cudaGetSymbolAddress((void**)&px2,   g_x2);
    cudaGetSymbolAddress((void**)&pff,   g_ff);
    cudaGetSymbolAddress((void**)&pwq,   g_wq);
    cudaGetSymbolAddress((void**)&pwk,   g_wk);
    cudaGetSymbolAddress((void**)&pwv,   g_wv);
    cudaGetSymbolAddress((void**)&pwo,   g_wo);
    cudaGetSymbolAddress((void**)&pw1,   g_w1);
    cudaGetSymbolAddress((void**)&pw2,   g_w2);

    const int SMEM_ATTN =
        (BQ_ * QSTR + 2 * BKT_ * QSTR + 2 * BKT_ * VSTR + BQ_ * SSTR + 3 * BQ_) * 4
        + 2 * BKT_ * 4;
    cudaFuncSetAttribute(attn_kernel,
                         cudaFuncAttributeMaxDynamicSharedMemorySize, SMEM_ATTN);

    // 0) weight conversion fp32 -> fp16 pair-interleaved
    {
        const int tot_dd  = (D_ / 2) * D_ / 4;       // 1M/2... = 524288
        const int tot_d1  = (D_ / 2) * DFF_ / 4;     // w1: K=D, N=DFF
        const int tot_2d  = (DFF_ / 2) * D_ / 4;     // w2: K=DFF, N=D
        cvt_pair_kernel<<<(tot_dd + 255) / 256, 256>>>(wq, pwq, D_,  tot_dd);
        cvt_pair_kernel<<<(tot_dd + 255) / 256, 256>>>(wk, pwk, D_,  tot_dd);
        cvt_pair_kernel<<<(tot_dd + 255) / 256, 256>>>(wv, pwv, D_,  tot_dd);
        cvt_pair_kernel<<<(tot_dd + 255) / 256, 256>>>(wo, pwo, D_,  tot_dd);
        cvt_pair_kernel<<<(tot_d1 + 255) / 256, 256>>>(w1, pw1, DFF_, tot_d1);
        cvt_pair_kernel<<<(tot_2d + 255) / 256, 256>>>(w2, pw2, D_,  tot_2d);
    }

    // 1) LN1 -> fp16
    ln_kernel<<<BS_, 256>>>(x, ln1_g, ln1_b, ph);

    // 2) Q, K, V projections (+bias, permute to [B,H,S,HD], fp32 out)
    dim3 gqkv(D_ / 128, BS_ / 128);
    hgemm_kernel<M_PERM><<<gqkv, 256>>>(ph, pwq, bq, nullptr, pq, BS_, D_, D_);
    hgemm_kernel<M_PERM><<<gqkv, 256>>>(ph, pwk, bk, nullptr, pk, BS_, D_, D_);
    hgemm_kernel<M_PERM><<<gqkv, 256>>>(ph, pwv, bv, nullptr, pv, BS_, D_, D_);

    // 3) causal attention (tf32 flash) -> fp16 attn
    attn_kernel<<<dim3(S_ / BQ_, H_, B_), 256, SMEM_ATTN>>>(pq, pk, pv, amask, pattn);

    // 4) output projection + residual (fp32 out)
    hgemm_kernel<M_RES><<<gqkv, 256>>>(pattn, pwo, bo, x, px2, BS_, D_, D_);

    // 5) LN2 -> fp16
    ln_kernel<<<BS_, 256>>>(px2, ln2_g, ln2_b, ph);

    // 6) FFN up + exact GELU -> fp16
    dim3 gff1(DFF_ / 128, BS_ / 128);
    hgemm_kernel<M_GELU><<<gff1, 256>>>(ph, pw1, b1, nullptr, pff, BS_, DFF_, D_);

    // 7) FFN down + residual -> fp32 output
    dim3 gff2(D_ / 128, BS_ / 128);
    hgemm_kernel<M_RES><<<gff2, 256>>>(pff, pw2, b2, px2, outp, BS_, D_, DFF_);
}

// round 14
// speedup vs baseline: 1.0009x; 1.0009x over previous
#include <cuda_runtime.h>
#include <cuda_fp16.h>
#include <math.h>
#include <stdint.h>

// Problem constants
#define B_   2
#define S_   2048
#define D_   2048
#define H_   16
#define HD_  128
#define DFF_ 8192
#define BS_  4096            // B_*S_
#define EPS_ 1e-5f

// ---------------- scratch (device globals; no allocations allowed) ----------
__device__ __half g_h   [BS_ * D_];       // LN out (fp16, feeds GEMMs only)
__device__ float  g_q   [BS_ * D_];       // Q in [B,H,S,HD] (fp32, attention)
__device__ float  g_k   [BS_ * D_];
__device__ float  g_v   [BS_ * D_];
__device__ __half g_attn[BS_ * D_];       // attn out (fp16, feeds WO GEMM)
__device__ float  g_x2  [BS_ * D_];       // residual after attention (fp32)
__device__ __half g_ff  [BS_ * DFF_];     // GELU out (fp16, feeds W2 GEMM)

// fp16 weights, pair-interleaved: Wp[kp][n] = {lo=W[2kp][n], hi=W[2kp+1][n]}
__device__ uint32_t g_wq[D_ * D_ / 2];
__device__ uint32_t g_wk[D_ * D_ / 2];
__device__ uint32_t g_wv[D_ * D_ / 2];
__device__ uint32_t g_wo[D_ * D_ / 2];
__device__ uint32_t g_w1[D_ * DFF_ / 2];
__device__ uint32_t g_w2[DFF_ * D_ / 2];

__device__ __forceinline__ uint32_t pack2(float lo, float hi) {
    __half2 h = __floats2half2_rn(lo, hi);
    return *reinterpret_cast<uint32_t*>(&h);
}

// ================= weight conversion: fp32 [K,N] -> u32 pairs [K/2,N] =======
__global__ void __launch_bounds__(256) cvt_pair_kernel(
    const float* __restrict__ W, uint32_t* __restrict__ Wp, int N, int total)
{
    const int i = blockIdx.x * 256 + threadIdx.x;   // one uint4 (4 pairs)
    if (i >= total) return;
    const int n4 = N >> 2;
    const int kp = i / n4;
    const int n0 = (i - kp * n4) * 4;
    const float4 r0 = *(const float4*)(W + (size_t)(2 * kp) * N + n0);
    const float4 r1 = *(const float4*)(W + (size_t)(2 * kp + 1) * N + n0);
    uint4 o;
    o.x = pack2(r0.x, r1.x);
    o.y = pack2(r0.y, r1.y);
    o.z = pack2(r0.z, r1.z);
    o.w = pack2(r0.w, r1.w);
    *(uint4*)(Wp + (size_t)kp * N + n0) = o;
}

// ============================ LayerNorm (fp16 out) ==========================
__global__ void __launch_bounds__(256) ln_kernel(const float* __restrict__ x,
                                                 const float* __restrict__ gam,
                                                 const float* __restrict__ bet,
                                                 __half* __restrict__ out)
{
    __shared__ float red[8];
    __shared__ float s_mu, s_rstd;
    const int row = blockIdx.x;
    const int t   = threadIdx.x;
    const float* xr = x + (size_t)row * D_;

    float4 v0 = *(const float4*)(xr + t * 4);
    float4 v1 = *(const float4*)(xr + 1024 + t * 4);

    float s = v0.x + v0.y + v0.z + v0.w + v1.x + v1.y + v1.z + v1.w;
    #pragma unroll
    for (int o = 16; o; o >>= 1) s += __shfl_xor_sync(0xffffffffu, s, o);
    if ((t & 31) == 0) red[t >> 5] = s;
    __syncthreads();
    if (t == 0) {
        float a = 0.f;
        #pragma unroll
        for (int i = 0; i < 8; i++) a += red[i];
        s_mu = a * (1.0f / D_);
    }
    __syncthreads();
    const float mu = s_mu;

    float dx[8];
    dx[0]=v0.x-mu; dx[1]=v0.y-mu; dx[2]=v0.z-mu; dx[3]=v0.w-mu;
    dx[4]=v1.x-mu; dx[5]=v1.y-mu; dx[6]=v1.z-mu; dx[7]=v1.w-mu;
    float sq = 0.f;
    #pragma unroll
    for (int i = 0; i < 8; i++) sq += dx[i]*dx[i];
    #pragma unroll
    for (int o = 16; o; o >>= 1) sq += __shfl_xor_sync(0xffffffffu, sq, o);
    __syncthreads();
    if ((t & 31) == 0) red[t >> 5] = sq;
    __syncthreads();
    if (t == 0) {
        float a = 0.f;
        #pragma unroll
        for (int i = 0; i < 8; i++) a += red[i];
        s_rstd = rsqrtf(a * (1.0f / D_) + EPS_);
    }
    __syncthreads();
    const float rstd = s_rstd;

    __half* orow = out + (size_t)row * D_;
    const int c0 = t * 4, c1 = 1024 + t * 4;
    float4 gv0 = *(const float4*)(gam + c0);
    float4 gv1 = *(const float4*)(gam + c1);
    float4 bv0 = *(const float4*)(bet + c0);
    float4 bv1 = *(const float4*)(bet + c1);
    uint2 p0, p1;
    p0.x = pack2(dx[0]*rstd*gv0.x + bv0.x, dx[1]*rstd*gv0.y + bv0.y);
    p0.y = pack2(dx[2]*rstd*gv0.z + bv0.z, dx[3]*rstd*gv0.w + bv0.w);
    p1.x = pack2(dx[4]*rstd*gv1.x + bv1.x, dx[5]*rstd*gv1.y + bv1.y);
    p1.y = pack2(dx[6]*rstd*gv1.z + bv1.z, dx[7]*rstd*gv1.w + bv1.w);
    *(uint2*)(orow + c0) = p0;
    *(uint2*)(orow + c1) = p1;
}

// ============================ common tensor-core helpers ====================
__device__ __forceinline__ uint32_t f2tf(float x) {
    uint32_t r;
    asm("cvt.rna.tf32.f32 %0, %1;" : "=r"(r) : "f"(x));
    return r;
}

__device__ __forceinline__ void mma8(float* c, const uint32_t* a, const uint32_t* b) {
    asm volatile(
        "mma.sync.aligned.m16n8k8.row.col.f32.tf32.tf32.f32 "
        "{%0,%1,%2,%3}, {%4,%5,%6,%7}, {%8,%9}, {%0,%1,%2,%3};"
        : "+f"(c[0]), "+f"(c[1]), "+f"(c[2]), "+f"(c[3])
        : "r"(a[0]), "r"(a[1]), "r"(a[2]), "r"(a[3]), "r"(b[0]), "r"(b[1]));
}

__device__ __forceinline__ void mma16(float* c, const uint32_t* a, const uint32_t* b) {
    asm volatile(
        "mma.sync.aligned.m16n8k16.row.col.f32.f16.f16.f32 "
        "{%0,%1,%2,%3}, {%4,%5,%6,%7}, {%8,%9}, {%0,%1,%2,%3};"
        : "+f"(c[0]), "+f"(c[1]), "+f"(c[2]), "+f"(c[3])
        : "r"(a[0]), "r"(a[1]), "r"(a[2]), "r"(a[3]), "r"(b[0]), "r"(b[1]));
}

#define CPA16(dst, src) \
    asm volatile("cp.async.cg.shared.global [%0], [%1], 16;\n" :: "r"(dst), "l"(src))

// ============================ FP16 tensor-core GEMM =========================
// C[M,N] = A[M,K] @ W[K,N] (+bias). A: fp16 row-major. W: u32 k-pair [K/2,N].
// 128x128x32 tile, 256 threads (8 warps 2x4, 64x32 warp tiles),
// mma.m16n8k16.f16, fp32 accum, cp.async double buffer.
#define M_PERM 0
#define M_RES  1
#define M_GELU 2

#define ASTRU 20    // u32 stride of A smem rows (16 kp + 4 pad) -> CF frags
#define BSTRU 136   // u32 stride of B smem rows -> CF frags

template<int MODE>
__global__ void __launch_bounds__(256) hgemm_kernel(
    const __half* __restrict__ A, const uint32_t* __restrict__ Wp,
    const float* __restrict__ bias, const float* __restrict__ res,
    void* __restrict__ outv, int M, int N, int K)
{
    __shared__ uint32_t As[2][128][ASTRU];   // 20.0 KB
    __shared__ uint32_t Bs[2][16][BSTRU];    // 17.0 KB

    const int t    = threadIdx.x;
    const int bm   = blockIdx.y * 128;
    const int bn   = blockIdx.x * 128;
    const int warp = t >> 5, lane = t & 31;
    const int wm   = warp >> 2, wn = warp & 3;   // 2x4 warp grid
    const int lg   = lane >> 2, lk = lane & 3;

    // A: slot i in {0,1}: row = (t>>2)+64i, 16B unit c = t&3 (8 fp16 = 4 kp)
    const int a_row = t >> 2, a_c = t & 3;
    // B: slot i: kp = (t>>5)+8i, n0 = 4*(t&31) u32
    const int b_kp = t >> 5, b_n = (t & 31) * 4;

    const uint32_t dA0 = (uint32_t)__cvta_generic_to_shared(&As[0][a_row][4 * a_c]);
    const uint32_t dA1 = (uint32_t)__cvta_generic_to_shared(&As[0][64 + a_row][4 * a_c]);
    const uint32_t dB0 = (uint32_t)__cvta_generic_to_shared(&Bs[0][b_kp][b_n]);
    const uint32_t dB1 = (uint32_t)__cvta_generic_to_shared(&Bs[0][8 + b_kp][b_n]);
    const uint32_t aBuf = 128 * ASTRU * 4;
    const uint32_t bBuf = 16 * BSTRU * 4;

    const __half*   gA0 = A + (size_t)(bm + a_row) * K + 8 * a_c;
    const __half*   gA1 = A + (size_t)(bm + 64 + a_row) * K + 8 * a_c;
    const uint32_t* gB0 = Wp + (size_t)b_kp * N + bn + b_n;
    const uint32_t* gB1 = Wp + (size_t)(8 + b_kp) * N + bn + b_n;

    float acc[4][4][4];
    #pragma unroll
    for (int i = 0; i < 4; i++)
        #pragma unroll
        for (int j = 0; j < 4; j++)
            #pragma unroll
            for (int r = 0; r < 4; r++) acc[i][j][r] = 0.f;

    const int KT = K >> 5;   // K-chunks of 32

    CPA16(dA0, gA0);
    CPA16(dA1, gA1);
    CPA16(dB0, gB0);
    CPA16(dB1, gB1);
    asm volatile("cp.async.commit_group;");

    int buf = 0;
    for (int kt = 0; kt < KT; ++kt) {
        if (kt + 1 < KT) {
            const uint32_t bo = (uint32_t)(buf ^ 1);
            const size_t ka = (size_t)(kt + 1) * 32;         // fp16 elems
            const size_t kb = (size_t)(kt + 1) * 16 * N;     // u32 elems
            CPA16(dA0 + bo * aBuf, gA0 + ka);
            CPA16(dA1 + bo * aBuf, gA1 + ka);
            CPA16(dB0 + bo * bBuf, gB0 + kb);
            CPA16(dB1 + bo * bBuf, gB1 + kb);
            asm volatile("cp.async.commit_group;");
            asm volatile("cp.async.wait_group 1;");
        } else {
            asm volatile("cp.async.wait_group 0;");
        }
        __syncthreads();

        #pragma unroll
        for (int s = 0; s < 2; ++s) {           // two k16 steps per chunk
            const int kb8 = s * 8;
            uint32_t af[4][4], bf[4][2];
            #pragma unroll
            for (int mt = 0; mt < 4; ++mt) {
                const uint32_t* ap = &As[buf][wm * 64 + mt * 16 + lg][kb8 + lk];
                af[mt][0] = ap[0];
                af[mt][1] = ap[8 * ASTRU];
                af[mt][2] = ap[4];
                af[mt][3] = ap[8 * ASTRU + 4];
            }
            #pragma unroll
            for (int nt = 0; nt < 4; ++nt) {
                const int col = wn * 32 + nt * 8 + lg;
                bf[nt][0] = Bs[buf][kb8 + lk][col];
                bf[nt][1] = Bs[buf][kb8 + lk + 4][col];
            }
            #pragma unroll
            for (int mt = 0; mt < 4; ++mt)
                #pragma unroll
                for (int nt = 0; nt < 4; ++nt)
                    mma16(acc[mt][nt], af[mt], bf[nt]);
        }
        __syncthreads();
        buf ^= 1;
    }

    // epilogue
    #pragma unroll
    for (int mt = 0; mt < 4; ++mt) {
        #pragma unroll
        for (int nt = 0; nt < 4; ++nt) {
            const int r0 = bm + wm * 64 + mt * 16 + lg;
            const int c  = bn + wn * 32 + nt * 8 + lk * 2;
            const float b0 = bias[c], b1 = bias[c + 1];
            #pragma unroll
            for (int half = 0; half < 2; ++half) {
                const int r = r0 + half * 8;
                float v0 = acc[mt][nt][half * 2 + 0] + b0;
                float v1 = acc[mt][nt][half * 2 + 1] + b1;
                if (MODE == M_PERM) {
                    float* out = (float*)outv;
                    const int bb = r >> 11, ss = r & (S_ - 1);
                    const int hh = c >> 7,  dd = c & (HD_ - 1);
                    const size_t idx = ((((size_t)bb * H_ + hh) * S_ + ss) << 7) + dd;
                    float2 w; w.x = v0; w.y = v1;
                    *(float2*)(out + idx) = w;
                } else if (MODE == M_RES) {
                    float* out = (float*)outv;
                    const size_t idx = (size_t)r * N + c;
                    float2 rv = *(const float2*)(res + idx);
                    float2 w; w.x = v0 + rv.x; w.y = v1 + rv.y;
                    *(float2*)(out + idx) = w;
                } else { // GELU (exact, erf) -> fp16
                    __half* out = (__half*)outv;
                    const size_t idx = (size_t)r * N + c;
                    const float g0 = 0.5f * v0 * (1.0f + erff(v0 * 0.70710678118654752f));
                    const float g1 = 0.5f * v1 * (1.0f + erff(v1 * 0.70710678118654752f));
                    *(uint32_t*)(out + idx) = pack2(g0, g1);
                }
            }
        }
    }
}

// ==================== TF32 tensor-core flash attention ======================
// grid (S/64, H, B), 256 threads (8 warps). BQ=64, BK=64, HD=128.
#define BQ_   64
#define BKT_  64
#define QSTR  132
#define VSTR  136
#define SSTR  68

__global__ void __launch_bounds__(256) attn_kernel(
    const float* __restrict__ Qg, const float* __restrict__ Kg,
    const float* __restrict__ Vg, const int* __restrict__ amask,
    __half* __restrict__ out)
{
    extern __shared__ float sm[];
    float* Qs   = sm;                              // 64*132 (tf32 bits)
    float* Ks   = Qs + BQ_ * QSTR;                 // 2 * 64*132
    float* Vs   = Ks + 2 * BKT_ * QSTR;            // 2 * 64*136
    float* Ss   = Vs + 2 * BKT_ * VSTR;            // 64*68
    float* mrow = Ss + BQ_ * SSTR;                 // 64
    float* lrow = mrow + BQ_;                      // 64
    float* arow = lrow + BQ_;                      // 64
    int*   msk  = (int*)(arow + BQ_);              // 2 * 64

    const int t    = threadIdx.x;
    const int warp = t >> 5, lane = t & 31;
    const int lg   = lane >> 2, lk = lane & 3;
    const int wm   = warp >> 1, wn = warp & 1;     // 4x2 warp grid
    const int bq0  = blockIdx.x * BQ_;
    const int h    = blockIdx.y;
    const int b    = blockIdx.z;
    const size_t base = ((size_t)(b * H_ + h) * S_) * HD_;
    const float scale = 0.08838834764831845f;      // 1/sqrt(128)

    const uint32_t ksb  = (uint32_t)__cvta_generic_to_shared(Ks);
    const uint32_t vsb  = (uint32_t)__cvta_generic_to_shared(Vs);
    const uint32_t mskb = (uint32_t)__cvta_generic_to_shared(msk);
    const uint32_t KBUF = BKT_ * QSTR * 4;
    const uint32_t VBUF = BKT_ * VSTR * 4;

    #pragma unroll
    for (int r = 0; r < 8; ++r) {
        const int e = t * 4 + r * 1024;
        const int row = e >> 7, col = e & 127;
        float4 v = *(const float4*)(Qg + base + (size_t)(bq0 + row) * HD_ + col);
        float* dst = &Qs[row * QSTR + col];
        dst[0] = __uint_as_float(f2tf(v.x * scale));
        dst[1] = __uint_as_float(f2tf(v.y * scale));
        dst[2] = __uint_as_float(f2tf(v.z * scale));
        dst[3] = __uint_as_float(f2tf(v.w * scale));
    }
    if (t < BQ_) { mrow[t] = -1e30f; lrow[t] = 0.0f; }

    const int nkt = blockIdx.x + 1;

    {
        const int k0 = 0;
        #pragma unroll
        for (int r = 0; r < 8; ++r) {
            const int e = t * 4 + r * 1024;
            const int row = e >> 7, col = e & 127;
            CPA16(ksb + (uint32_t)(row * QSTR + col) * 4,
                  Kg + base + (size_t)(k0 + row) * HD_ + col);
            CPA16(vsb + (uint32_t)(row * VSTR + col) * 4,
                  Vg + base + (size_t)(k0 + row) * HD_ + col);
        }
        if (t < 16) CPA16(mskb + t * 16, amask + b * S_ + k0 + t * 4);
        asm volatile("cp.async.commit_group;");
    }

    float o[8][4];
    #pragma unroll
    for (int i = 0; i < 8; i++)
        #pragma unroll
        for (int r = 0; r < 4; r++) o[i][r] = 0.f;

    const int r0  = 16 * wm + lg;
    const uint32_t* Qu = (const uint32_t*)Qs;

    int buf = 0;
    for (int kt = 0; kt < nkt; ++kt) {
        const int k0 = kt * BKT_;
        asm volatile("cp.async.wait_group 0;");
        __syncthreads();

        if (kt + 1 < nkt) {
            const int kn = (kt + 1) * BKT_;
            const uint32_t bo = (uint32_t)(buf ^ 1);
            #pragma unroll
            for (int r = 0; r < 8; ++r) {
                const int e = t * 4 + r * 1024;
                const int row = e >> 7, col = e & 127;
                CPA16(ksb + bo * KBUF + (uint32_t)(row * QSTR + col) * 4,
                      Kg + base + (size_t)(kn + row) * HD_ + col);
                CPA16(vsb + bo * VBUF + (uint32_t)(row * VSTR + col) * 4,
                      Vg + base + (size_t)(kn + row) * HD_ + col);
            }
            if (t < 16) CPA16(mskb + bo * 256 + t * 16, amask + b * S_ + kn + t * 4);
            asm volatile("cp.async.commit_group;");
        }

        const float* Kb = Ks + buf * BKT_ * QSTR;
        const float* Vb = Vs + buf * BKT_ * VSTR;
        const int*   mb = msk + buf * BKT_;

        float c[4][4];
        #pragma unroll
        for (int i = 0; i < 4; i++)
            #pragma unroll
            for (int r = 0; r < 4; r++) c[i][r] = 0.f;

        #pragma unroll
        for (int k8 = 0; k8 < HD_; k8 += 8) {
            uint32_t af[4], bfv[4][2];
            const uint32_t* qp = &Qu[r0 * QSTR + k8 + lk];
            af[0] = qp[0];
            af[1] = qp[8 * QSTR];
            af[2] = qp[4];
            af[3] = qp[8 * QSTR + 4];
            #pragma unroll
            for (int nt = 0; nt < 4; ++nt) {
                const int col = 32 * wn + nt * 8 + lg;
                bfv[nt][0] = f2tf(Kb[col * QSTR + k8 + lk]);
                bfv[nt][1] = f2tf(Kb[col * QSTR + k8 + lk + 4]);
            }
            #pragma unroll
            for (int nt = 0; nt < 4; ++nt) mma8(c[nt], af, bfv[nt]);
        }

        const bool diag = (kt == nkt - 1);
        const int qg0 = bq0 + r0, qg1 = qg0 + 8;
        #pragma unroll
        for (int nt = 0; nt < 4; ++nt) {
            const int jl0 = 32 * wn + nt * 8 + 2 * lk;
            const int jl1 = jl0 + 1;
            const int jg0 = k0 + jl0, jg1 = jg0 + 1;
            const bool m0 = (mb[jl0] != 0), m1 = (mb[jl1] != 0);
            const bool v00 = m0 && (!diag || jg0 <= qg0);
            const bool v01 = m1 && (!diag || jg1 <= qg0);
            const bool v10 = m0 && (!diag || jg0 <= qg1);
            const bool v11 = m1 && (!diag || jg1 <= qg1);
            Ss[r0 * SSTR + jl0]       = v00 ? c[nt][0] : -1e30f;
            Ss[r0 * SSTR + jl1]       = v01 ? c[nt][1] : -1e30f;
            Ss[(r0 + 8) * SSTR + jl0] = v10 ? c[nt][2] : -1e30f;
            Ss[(r0 + 8) * SSTR + jl1] = v11 ? c[nt][3] : -1e30f;
        }
        __syncthreads();

        {
            const int sr  = t >> 2;
            const int sc0 = (t & 3) * 16;
            float4 va = *(const float4*)&Ss[sr * SSTR + sc0];
            float4 vb = *(const float4*)&Ss[sr * SSTR + sc0 + 4];
            float4 vc = *(const float4*)&Ss[sr * SSTR + sc0 + 8];
            float4 vd = *(const float4*)&Ss[sr * SSTR + sc0 + 12];
            float tmax = fmaxf(fmaxf(fmaxf(va.x, va.y), fmaxf(va.z, va.w)),
                               fmaxf(fmaxf(vb.x, vb.y), fmaxf(vb.z, vb.w)));
            tmax = fmaxf(tmax,
                   fmaxf(fmaxf(fmaxf(vc.x, vc.y), fmaxf(vc.z, vc.w)),
                         fmaxf(fmaxf(vd.x, vd.y), fmaxf(vd.z, vd.w))));
            tmax = fmaxf(tmax, __shfl_xor_sync(0xffffffffu, tmax, 1));
            tmax = fmaxf(tmax, __shfl_xor_sync(0xffffffffu, tmax, 2));
            const float mo = mrow[sr];
            const float nm = fmaxf(mo, tmax);
            va.x = __expf(va.x - nm); va.y = __expf(va.y - nm);
            va.z = __expf(va.z - nm); va.w = __expf(va.w - nm);
            vb.x = __expf(vb.x - nm); vb.y = __expf(vb.y - nm);
            vb.z = __expf(vb.z - nm); vb.w = __expf(vb.w - nm);
            vc.x = __expf(vc.x - nm); vc.y = __expf(vc.y - nm);
            vc.z = __expf(vc.z - nm); vc.w = __expf(vc.w - nm);
            vd.x = __expf(vd.x - nm); vd.y = __expf(vd.y - nm);
            vd.z = __expf(vd.z - nm); vd.w = __expf(vd.w - nm);
            float sum = va.x + va.y + va.z + va.w + vb.x + vb.y + vb.z + vb.w +
                        vc.x + vc.y + vc.z + vc.w + vd.x + vd.y + vd.z + vd.w;
            *(float4*)&Ss[sr * SSTR + sc0]      = va;
            *(float4*)&Ss[sr * SSTR + sc0 + 4]  = vb;
            *(float4*)&Ss[sr * SSTR + sc0 + 8]  = vc;
            *(float4*)&Ss[sr * SSTR + sc0 + 12] = vd;
            sum += __shfl_xor_sync(0xffffffffu, sum, 1);
            sum += __shfl_xor_sync(0xffffffffu, sum, 2);
            if ((t & 3) == 0) {
                const float al = __expf(mo - nm);
                arow[sr] = al;
                lrow[sr] = lrow[sr] * al + sum;
                mrow[sr] = nm;
            }
        }
        __syncthreads();

        const float al0 = arow[r0];
        const float al1 = arow[r0 + 8];
        #pragma unroll
        for (int nt = 0; nt < 8; ++nt) {
            o[nt][0] *= al0; o[nt][1] *= al0;
            o[nt][2] *= al1; o[nt][3] *= al1;
        }
        #pragma unroll
        for (int k8 = 0; k8 < BKT_; k8 += 8) {
            uint32_t af[4], bfv[8][2];
            const float* pp = &Ss[r0 * SSTR + k8 + lk];
            af[0] = f2tf(pp[0]);
            af[1] = f2tf(pp[8 * SSTR]);
            af[2] = f2tf(pp[4]);
            af[3] = f2tf(pp[8 * SSTR + 4]);
            #pragma unroll
            for (int nt = 0; nt < 8; ++nt) {
                const int n = 64 * wn + nt * 8 + lg;
                bfv[nt][0] = f2tf(Vb[(k8 + lk) * VSTR + n]);
                bfv[nt][1] = f2tf(Vb[(k8 + lk + 4) * VSTR + n]);
            }
            #pragma unroll
            for (int nt = 0; nt < 8; ++nt) mma8(o[nt], af, bfv[nt]);
        }
        buf ^= 1;
    }

    // epilogue: normalize, write fp16 to [B,S,D] with head de-interleave
    const float inv0 = 1.0f / lrow[r0];
    const float inv1 = 1.0f / lrow[r0 + 8];
    #pragma unroll
    for (int nt = 0; nt < 8; ++nt) {
        const int col = 64 * wn + nt * 8 + 2 * lk;
        const size_t base0 = ((size_t)b * S_ + bq0 + r0) * D_ + h * HD_ + col;
        const size_t base1 = base0 + (size_t)8 * D_;
        *(uint32_t*)(out + base0) = pack2(o[nt][0] * inv0, o[nt][1] * inv0);
        *(uint32_t*)(out + base1) = pack2(o[nt][2] * inv1, o[nt][3] * inv1);
    }
}

// ============================ launch ========================================
extern "C" void kernel_launch(void* const* d_in, const int* in_sizes, int n_in,
                              void* d_out, int out_size)
{
    const float* x     = (const float*)d_in[0];
    const int*   amask = (const int*)  d_in[1];
    const float* ln1_g = (const float*)d_in[2];
    const float* ln1_b = (const float*)d_in[3];
    const float* wq    = (const float*)d_in[4];
    const float* bq    = (const float*)d_in[5];
    const float* wk    = (const float*)d_in[6];
    const float* bk    = (const float*)d_in[7];
    const float* wv    = (const float*)d_in[8];
    const float* bv    = (const float*)d_in[9];
    const float* wo    = (const float*)d_in[10];
    const float* bo    = (const float*)d_in[11];
    const float* ln2_g = (const float*)d_in[12];
    const float* ln2_b = (const float*)d_in[13];
    const float* w1    = (const float*)d_in[14];
    const float* b1    = (const float*)d_in[15];
    const float* w2    = (const float*)d_in[16];
    const float* b2    = (const float*)d_in[17];
    float* outp = (float*)d_out;

    __half *ph, *pattn, *pff;
    float *pq, *pk, *pv, *px2;
    uint32_t *pwq, *pwk, *pwv, *pwo, *pw1, *pw2;
    cudaGetSymbolAddress((void**)&ph,    g_h);
    cudaGetSymbolAddress((void**)&pq,    g_q);
    cudaGetSymbolAddress((void**)&pk,    g_k);
    cudaGetSymbolAddress((void**)&pv,    g_v);
    cudaGetSymbolAddress((void**)&pattn, g_attn);
    cudaGetSymbolAddress((void**)&px2,   g_x2);
    cudaGetSymbolAddress((void**)&pff,   g_ff);
    cudaGetSymbolAddress((void**)&pwq,   g_wq);
    cudaGetSymbolAddress((void**)&pwk,   g_wk);
    cudaGetSymbolAddress((void**)&pwv,   g_wv);
    cudaGetSymbolAddress((void**)&pwo,   g_wo);
    cudaGetSymbolAddress((void**)&pw1,   g_w1);
    cudaGetSymbolAddress((void**)&pw2,   g_w2);

    const int SMEM_ATTN =
        (BQ_ * QSTR + 2 * BKT_ * QSTR + 2 * BKT_ * VSTR + BQ_ * SSTR + 3 * BQ_) * 4
        + 2 * BKT_ * 4;
    cudaFuncSetAttribute(attn_kernel,
                         cudaFuncAttributeMaxDynamicSharedMemorySize, SMEM_ATTN);

    // 0) weight conversion fp32 -> fp16 pair-interleaved
    {
        const int tot_dd  = (D_ / 2) * D_ / 4;       // 1M/2... = 524288
        const int tot_d1  = (D_ / 2) * DFF_ / 4;     // w1: K=D, N=DFF
        const int tot_2d  = (DFF_ / 2) * D_ / 4;     // w2: K=DFF, N=D
        cvt_pair_kernel<<<(tot_dd + 255) / 256, 256>>>(wq, pwq, D_,  tot_dd);
        cvt_pair_kernel<<<(tot_dd + 255) / 256, 256>>>(wk, pwk, D_,  tot_dd);
        cvt_pair_kernel<<<(tot_dd + 255) / 256, 256>>>(wv, pwv, D_,  tot_dd);
        cvt_pair_kernel<<<(tot_dd + 255) / 256, 256>>>(wo, pwo, D_,  tot_dd);
        cvt_pair_kernel<<<(tot_d1 + 255) / 256, 256>>>(w1, pw1, DFF_, tot_d1);
        cvt_pair_kernel<<<(tot_2d + 255) / 256, 256>>>(w2, pw2, D_,  tot_2d);
    }

    // 1) LN1 -> fp16
    ln_kernel<<<BS_, 256>>>(x, ln1_g, ln1_b, ph);

    // 2) Q, K, V projections (+bias, permute to [B,H,S,HD], fp32 out)
    dim3 gqkv(D_ / 128, BS_ / 128);
    hgemm_kernel<M_PERM><<<gqkv, 256>>>(ph, pwq, bq, nullptr, pq, BS_, D_, D_);
    hgemm_kernel<M_PERM><<<gqkv, 256>>>(ph, pwk, bk, nullptr, pk, BS_, D_, D_);
    hgemm_kernel<M_PERM><<<gqkv, 256>>>(ph, pwv, bv, nullptr, pv, BS_, D_, D_);

    // 3) causal attention (tf32 flash) -> fp16 attn
    attn_kernel<<<dim3(S_ / BQ_, H_, B_), 256, SMEM_ATTN>>>(pq, pk, pv, amask, pattn);

    // 4) output projection + residual (fp32 out)
    hgemm_kernel<M_RES><<<gqkv, 256>>>(pattn, pwo, bo, x, px2, BS_, D_, D_);

    // 5) LN2 -> fp16
    ln_kernel<<<BS_, 256>>>(px2, ln2_g, ln2_b, ph);

    // 6) FFN up + exact GELU -> fp16
    dim3 gff1(DFF_ / 128, BS_ / 128);
    hgemm_kernel<M_GELU><<<gff1, 256>>>(ph, pw1, b1, nullptr, pff, BS_, DFF_, D_);

    // 7) FFN down + residual -> fp32 output
    dim3 gff2(D_ / 128, BS_ / 128);
    hgemm_kernel<M_RES><<<gff2, 256>>>(pff, pw2, b2, px2, outp, BS_, D_, DFF_);
}